// round 2
// baseline (speedup 1.0000x reference)
#include <cuda_runtime.h>
#include <cstdint>

#define Bn 8
#define Nn 8192
#define Sn 1024
#define Kn 32
#define C1c 64
#define C3c 128
#define Pn (Bn*Sn*Kn)   /* 262144 positions */
#define R2 0.04f

// ---------------- device scratch (no runtime allocations allowed) ---------
static __device__ int   g_idx[Pn];
static __device__ float g_y1[(size_t)Pn*C1c];
static __device__ float g_y2[(size_t)Pn*C1c];
static __device__ float g_ymax[Bn*Sn*C3c];
static __device__ float g_ymin[Bn*Sn*C3c];
static __device__ float g_sum1[C1c], g_sq1[C1c], g_sum2[C1c], g_sq2[C1c];
static __device__ float g_sum3[C3c], g_sq3[C3c];
static __device__ float g_sc1[C1c], g_sh1[C1c], g_sc2[C1c], g_sh2[C1c];
static __device__ float g_sc3[C3c], g_sh3[C3c];

// ---------------- packed f32x2 helpers (rn, NO fma contraction) -----------
typedef unsigned long long u64p;
__device__ __forceinline__ u64p f2pack(float lo, float hi){ u64p r; asm("mov.b64 %0,{%1,%2};":"=l"(r):"f"(lo),"f"(hi)); return r; }
__device__ __forceinline__ void f2unpack(u64p v, float& lo, float& hi){ asm("mov.b64 {%0,%1},%2;":"=f"(lo),"=f"(hi):"l"(v)); }
__device__ __forceinline__ u64p f2add(u64p a, u64p b){ u64p r; asm("add.rn.f32x2 %0,%1,%2;":"=l"(r):"l"(a),"l"(b)); return r; }
__device__ __forceinline__ u64p f2mul(u64p a, u64p b){ u64p r; asm("mul.rn.f32x2 %0,%1,%2;":"=l"(r):"l"(a),"l"(b)); return r; }

// ============================ FPS =========================================
#define FPT 16
#define FTH 512
__global__ __launch_bounds__(FTH,1) void k_fps(const float* __restrict__ x,
                                               float* __restrict__ newx){
    __shared__ float sWarpMax[FTH/32];
    __shared__ int   sBest[2];
    const int b = blockIdx.x, tid = threadIdx.x, lane = tid & 31, wid = tid >> 5;
    const float* xb = x + (size_t)b*Nn*3;
    float* nx = newx + (size_t)b*Sn*3;
    const int n0 = tid*FPT;

    u64p xq[FPT/2], yq[FPT/2], zq[FPT/2];
    float dist[FPT];
    #pragma unroll
    for (int i=0;i<FPT/2;i++){
        const float* p = xb + (size_t)(n0+2*i)*3;
        xq[i]=f2pack(p[0],p[3]); yq[i]=f2pack(p[1],p[4]); zq[i]=f2pack(p[2],p[5]);
    }
    #pragma unroll
    for (int i=0;i<FPT;i++) dist[i]=1e10f;
    if (tid==0) sBest[0]=0x7fffffff;
    __syncthreads();

    int farthest = 0;
    for (int s=0;s<Sn;s++){
        const float* cp = xb + (size_t)farthest*3;
        const float cx=cp[0], cy=cp[1], cz=cp[2];
        if (tid==0){ float* o = nx + s*3; o[0]=cx; o[1]=cy; o[2]=cz; }
        const u64p ncx=f2pack(-cx,-cx), ncy=f2pack(-cy,-cy), ncz=f2pack(-cz,-cz);
        float tmax = -3.4e38f;
        #pragma unroll
        for (int i=0;i<FPT/2;i++){
            u64p dx=f2add(xq[i],ncx), dy=f2add(yq[i],ncy), dz=f2add(zq[i],ncz);
            u64p d2=f2add(f2add(f2mul(dx,dx),f2mul(dy,dy)),f2mul(dz,dz));
            float a,bb; f2unpack(d2,a,bb);
            dist[2*i]   = fminf(dist[2*i],a);
            dist[2*i+1] = fminf(dist[2*i+1],bb);
            tmax = fmaxf(tmax, fmaxf(dist[2*i], dist[2*i+1]));
        }
        float wm = tmax;
        #pragma unroll
        for (int o=16;o>0;o>>=1) wm=fmaxf(wm,__shfl_xor_sync(0xffffffffu,wm,o));
        if (lane==0) sWarpMax[wid]=wm;
        __syncthreads();
        const int buf = s & 1;
        if (tid==0) sBest[1-buf]=0x7fffffff;
        float v = (lane < FTH/32)? sWarpMax[lane] : -3.4e38f;
        #pragma unroll
        for (int o=16;o>0;o>>=1) v=fmaxf(v,__shfl_xor_sync(0xffffffffu,v,o));
        if (tmax==v){
            int cand = 0x7fffffff;
            #pragma unroll
            for (int j=FPT-1;j>=0;j--){ if (dist[j]==v) cand = n0+j; }
            atomicMin(&sBest[buf], cand);
        }
        __syncthreads();
        farthest = sBest[buf];
    }
}

// ============================ Ball query ==================================
__global__ __launch_bounds__(256) void k_ball(const float* __restrict__ x,
                                              const float* __restrict__ newx){
    const int w = blockIdx.x*(256/32) + (threadIdx.x>>5);
    const int lane = threadIdx.x & 31;
    const int b = w >> 10;
    const float* c = newx + (size_t)w*3;
    const float cx=c[0], cy=c[1], cz=c[2];
    const float cn = __fadd_rn(__fadd_rn(__fmul_rn(cx,cx),__fmul_rn(cy,cy)),__fmul_rn(cz,cz));
    const float* xb = x + (size_t)b*Nn*3;
    int total=0, first=0;
    for (int base=0; base<Nn && total<Kn; base+=32){
        const int n = base + lane;
        const float* p = xb + (size_t)n*3;
        const float px=p[0], py=p[1], pz=p[2];
        const float dot = __fadd_rn(__fadd_rn(__fmul_rn(cx,px),__fmul_rn(cy,py)),__fmul_rn(cz,pz));
        const float pn  = __fadd_rn(__fadd_rn(__fmul_rn(px,px),__fmul_rn(py,py)),__fmul_rn(pz,pz));
        const float sq  = __fadd_rn(__fadd_rn(__fmul_rn(-2.0f,dot),cn),pn);
        const bool pred = !(sq > R2);
        const unsigned mask = __ballot_sync(0xffffffffu, pred);
        if (total==0 && mask) first = base + __ffs(mask) - 1;
        const int slot = total + __popc(mask & ((1u<<lane)-1u));
        if (pred && slot < Kn) g_idx[w*Kn + slot] = n;
        total += __popc(mask);
    }
    if (total < Kn && lane >= total) g_idx[w*Kn + lane] = first;
}

// ============================ misc ========================================
__global__ void k_init(){
    const int t=threadIdx.x;
    if (t<C1c){ g_sum1[t]=0.f; g_sq1[t]=0.f; g_sum2[t]=0.f; g_sq2[t]=0.f; }
    if (t<C3c){ g_sum3[t]=0.f; g_sq3[t]=0.f; }
}
__device__ __forceinline__ void bn_fin(int t, const float* g, const float* be,
                                       const float* sums, const float* sqs,
                                       float* sc, float* sh){
    const float inv = 1.0f/(float)Pn;           // power of two: exact
    const float m = sums[t]*inv;
    const float v = fmaxf(sqs[t]*inv - m*m, 0.f);
    const float s = g[t]*rsqrtf(v + 1e-5f);
    sc[t] = s; sh[t] = fmaf(-m, s, be[t]);
}
__global__ void k_f1(const float* g, const float* be){ const int t=threadIdx.x; if (t<C1c) bn_fin(t,g,be,g_sum1,g_sq1,g_sc1,g_sh1); }
__global__ void k_f2(const float* g, const float* be){ const int t=threadIdx.x; if (t<C1c) bn_fin(t,g,be,g_sum2,g_sq2,g_sc2,g_sh2); }
__global__ void k_f3(const float* g, const float* be){ const int t=threadIdx.x; if (t<C3c) bn_fin(t,g,be,g_sum3,g_sq3,g_sc3,g_sh3); }

// ============================ Layer 1 (3->64) + stats =====================
__global__ __launch_bounds__(256) void k_l1(const float* __restrict__ x,
                                            const float* __restrict__ newx,
                                            const float* __restrict__ W1,
                                            const float* __restrict__ b1){
    __shared__ float sh[128][3];
    __shared__ float redS[4][64], redQ[4][64];
    const int tid = threadIdx.x;
    const int p0  = blockIdx.x*128;
    if (tid < 128){
        const int p = p0 + tid;
        const int iv = g_idx[p];
        const int b = p >> 15;
        const int s = (p >> 5) & 1023;
        const float* pt = x    + ((size_t)b*Nn + iv)*3;
        const float* cc = newx + ((size_t)b*Sn + s)*3;
        sh[tid][0]=pt[0]-cc[0]; sh[tid][1]=pt[1]-cc[1]; sh[tid][2]=pt[2]-cc[2];
    }
    __syncthreads();
    const int c = tid & 63, pg = tid >> 6;
    const float w0=W1[c*3], w1=W1[c*3+1], w2=W1[c*3+2], bb=b1[c];
    float sm=0.f, sq=0.f;
    #pragma unroll 8
    for (int j=0;j<32;j++){
        const int pl = pg*32 + j;
        const float y = fmaf(sh[pl][0],w0, fmaf(sh[pl][1],w1, fmaf(sh[pl][2],w2, bb)));
        g_y1[(size_t)(p0+pl)*64 + c] = y;
        sm += y; sq = fmaf(y,y,sq);
    }
    redS[pg][c]=sm; redQ[pg][c]=sq;
    __syncthreads();
    if (tid < 64){
        atomicAdd(&g_sum1[tid], redS[0][tid]+redS[1][tid]+redS[2][tid]+redS[3][tid]);
        atomicAdd(&g_sq1[tid],  redQ[0][tid]+redQ[1][tid]+redQ[2][tid]+redQ[3][tid]);
    }
}

// ============================ Layer 2 (64->64) + stats ====================
__global__ __launch_bounds__(256) void k_l2(const float* __restrict__ W2,
                                            const float* __restrict__ b2){
    __shared__ float sW[64][65];     // [ci][c], padded
    __shared__ float sh[64][64];     // [pos][ci]
    __shared__ float ssc[64], ssh[64];
    __shared__ float redS[4][64], redQ[4][64];
    const int tid=threadIdx.x;
    const int p0 = blockIdx.x*64;
    if (tid<64){ ssc[tid]=g_sc1[tid]; ssh[tid]=g_sh1[tid]; }
    #pragma unroll
    for (int j=0;j<16;j++){ const int l=tid+j*256; sW[l&63][l>>6]=W2[l]; }
    __syncthreads();
    #pragma unroll
    for (int j=0;j<16;j++){
        const int l=tid+j*256; const int pos=l>>6, ci=l&63;
        float v = g_y1[(size_t)p0*64 + l];
        sh[pos][ci] = fmaxf(fmaf(ssc[ci], v, ssh[ci]), 0.f);
    }
    __syncthreads();
    const int c = tid&63, pg=tid>>6;
    const float bb=b2[c];
    float y[16];
    #pragma unroll
    for (int i=0;i<16;i++) y[i]=bb;
    #pragma unroll
    for (int ci0=0; ci0<64; ci0+=4){
        const float w0=sW[ci0][c], w1=sW[ci0+1][c], w2=sW[ci0+2][c], w3=sW[ci0+3][c];
        #pragma unroll
        for (int i=0;i<16;i++){
            const float4 h4 = *(const float4*)&sh[pg*16+i][ci0];
            y[i] = fmaf(w0,h4.x, fmaf(w1,h4.y, fmaf(w2,h4.z, fmaf(w3,h4.w, y[i]))));
        }
    }
    float sm=0.f, sq=0.f;
    #pragma unroll
    for (int i=0;i<16;i++){
        g_y2[(size_t)(p0+pg*16+i)*64 + c] = y[i];
        sm += y[i]; sq = fmaf(y[i],y[i],sq);
    }
    redS[pg][c]=sm; redQ[pg][c]=sq;
    __syncthreads();
    if (tid<64){
        atomicAdd(&g_sum2[tid], redS[0][tid]+redS[1][tid]+redS[2][tid]+redS[3][tid]);
        atomicAdd(&g_sq2[tid],  redQ[0][tid]+redQ[1][tid]+redQ[2][tid]+redQ[3][tid]);
    }
}

// ============================ Layer 3 (64->128) + stats + pooled ==========
__global__ __launch_bounds__(256) void k_l3(const float* __restrict__ W3,
                                            const float* __restrict__ b3){
    __shared__ float sW[64][129];    // [ci][o], padded
    __shared__ float sh[32][64];     // [pos][ci] — one (b,s) group per block
    __shared__ float ssc[64], ssh[64];
    __shared__ float redS[2][128], redQ[2][128], redM[2][128], redN[2][128];
    const int tid=threadIdx.x;
    const int p0 = blockIdx.x*32;
    if (tid<64){ ssc[tid]=g_sc2[tid]; ssh[tid]=g_sh2[tid]; }
    #pragma unroll
    for (int j=0;j<32;j++){ const int l=tid+j*256; sW[l&63][l>>6]=W3[l]; }
    __syncthreads();
    #pragma unroll
    for (int j=0;j<8;j++){
        const int l=tid+j*256; const int pos=l>>6, ci=l&63;
        float v = g_y2[(size_t)p0*64 + l];
        sh[pos][ci] = fmaxf(fmaf(ssc[ci], v, ssh[ci]), 0.f);
    }
    __syncthreads();
    const int c = tid&127, pg=tid>>7;
    const float bb=b3[c];
    float y[16];
    #pragma unroll
    for (int i=0;i<16;i++) y[i]=bb;
    #pragma unroll
    for (int ci0=0; ci0<64; ci0+=4){
        const float w0=sW[ci0][c], w1=sW[ci0+1][c], w2=sW[ci0+2][c], w3=sW[ci0+3][c];
        #pragma unroll
        for (int i=0;i<16;i++){
            const float4 h4 = *(const float4*)&sh[pg*16+i][ci0];
            y[i] = fmaf(w0,h4.x, fmaf(w1,h4.y, fmaf(w2,h4.z, fmaf(w3,h4.w, y[i]))));
        }
    }
    float sm=0.f, sq=0.f, mx=-3.4e38f, mn=3.4e38f;
    #pragma unroll
    for (int i=0;i<16;i++){
        sm += y[i]; sq = fmaf(y[i],y[i],sq);
        mx = fmaxf(mx,y[i]); mn = fminf(mn,y[i]);
    }
    redS[pg][c]=sm; redQ[pg][c]=sq; redM[pg][c]=mx; redN[pg][c]=mn;
    __syncthreads();
    if (tid<128){
        g_ymax[(size_t)blockIdx.x*128 + tid] = fmaxf(redM[0][tid], redM[1][tid]);
        g_ymin[(size_t)blockIdx.x*128 + tid] = fminf(redN[0][tid], redN[1][tid]);
        atomicAdd(&g_sum3[tid], redS[0][tid]+redS[1][tid]);
        atomicAdd(&g_sq3[tid],  redQ[0][tid]+redQ[1][tid]);
    }
}

// ============================ Output ======================================
__global__ __launch_bounds__(256) void k_out(float* __restrict__ feat){
    const int i = blockIdx.x*256 + threadIdx.x;
    const int c = i & 127;
    const float sc = g_sc3[c], sh = g_sh3[c];
    const float v = (sc >= 0.f) ? g_ymax[i] : g_ymin[i];
    feat[i] = fmaxf(fmaf(sc, v, sh), 0.f);
}

// ============================ launch ======================================
extern "C" void kernel_launch(void* const* d_in, const int* in_sizes, int n_in,
                              void* d_out, int out_size){
    const float* x  = (const float*)d_in[0];
    const float* W1 = (const float*)d_in[1];  const float* b1 = (const float*)d_in[2];
    const float* g1 = (const float*)d_in[3];  const float* be1= (const float*)d_in[4];
    const float* W2 = (const float*)d_in[5];  const float* b2 = (const float*)d_in[6];
    const float* g2 = (const float*)d_in[7];  const float* be2= (const float*)d_in[8];
    const float* W3 = (const float*)d_in[9];  const float* b3 = (const float*)d_in[10];
    const float* g3 = (const float*)d_in[11]; const float* be3= (const float*)d_in[12];
    float* out  = (float*)d_out;
    float* newx = out;                 // (8,1024,3)
    float* feat = out + Bn*Sn*3;       // (8,1024,128)

    k_init<<<1,128>>>();
    k_fps <<<Bn,FTH>>>(x, newx);
    k_ball<<<Sn*Bn/8,256>>>(x, newx);
    k_l1  <<<Pn/128,256>>>(x, newx, W1, b1);
    k_f1  <<<1,64>>>(g1,be1);
    k_l2  <<<Pn/64,256>>>(W2,b2);
    k_f2  <<<1,64>>>(g2,be2);
    k_l3  <<<Pn/32,256>>>(W3,b3);
    k_f3  <<<1,128>>>(g3,be3);
    k_out <<<Pn*C3c/Kn/256,256>>>(feat);
}